// round 2
// baseline (speedup 1.0000x reference)
#include <cuda_runtime.h>
#include <cuda_bf16.h>
#include <cstdint>

// out[row, :] = weight[indices[row], :]
// rows = 8*2048 = 16384, D = 1024 fp32 = 256 float4 per row.
// One CTA per row, 256 threads, one float4 per thread.
// NOTE: indices are int32 (jax x64-disabled downgrades jnp.int64 -> int32).
__global__ void __launch_bounds__(256, 8)
gather_rows_kernel(const int* __restrict__ indices,
                   const float4* __restrict__ weight,
                   float4* __restrict__ out)
{
    const int row = blockIdx.x;
    // Uniform (broadcast) load of the row index for this CTA.
    const int id = __ldg(&indices[row]);

    const float4* __restrict__ src = weight + (size_t)id * 256;
    float4* __restrict__ dst = out + (size_t)row * 256;

    dst[threadIdx.x] = __ldg(&src[threadIdx.x]);
}

extern "C" void kernel_launch(void* const* d_in, const int* in_sizes, int n_in,
                              void* d_out, int out_size)
{
    // metadata order: indices (int32, 8*2048), weight (float32, 50304*1024)
    const int*    indices = (const int*)d_in[0];
    const float4* weight  = (const float4*)d_in[1];
    float4*       out     = (float4*)d_out;

    const int rows = in_sizes[0];          // 16384
    gather_rows_kernel<<<rows, 256>>>(indices, weight, out);
}

// round 3
// speedup vs baseline: 1.6831x; 1.6831x over previous
#include <cuda_runtime.h>
#include <cuda_bf16.h>
#include <cstdint>

// out[row, :] = weight[indices[row], :]
// rows = 16384, D = 1024 fp32 = 256 float4 per row.
// 8 rows per CTA, 256 threads: each thread issues 8 independent LDG.128
// (MLP=8) then 8 streaming STG.128. Indices staged through smem.
constexpr int ROWS_PER_CTA = 8;

__device__ __forceinline__ void stg_cs(float4* p, float4 v) {
    asm volatile("st.global.cs.v4.f32 [%0], {%1, %2, %3, %4};"
                 :: "l"(p), "f"(v.x), "f"(v.y), "f"(v.z), "f"(v.w)
                 : "memory");
}

__global__ void __launch_bounds__(256)
gather_rows_kernel(const int* __restrict__ indices,
                   const float4* __restrict__ weight,
                   float4* __restrict__ out)
{
    __shared__ int sidx[ROWS_PER_CTA];

    const int base_row = blockIdx.x * ROWS_PER_CTA;
    if (threadIdx.x < ROWS_PER_CTA)
        sidx[threadIdx.x] = __ldg(&indices[base_row + threadIdx.x]);
    __syncthreads();

    const int tid = threadIdx.x;

    // Front-batch 8 independent 16B loads (MLP=8 per thread).
    float4 v[ROWS_PER_CTA];
#pragma unroll
    for (int r = 0; r < ROWS_PER_CTA; r++) {
        const size_t src = (size_t)sidx[r] * 256 + tid;
        v[r] = __ldg(&weight[src]);
    }

    // Streaming stores: write-once output, keep L2 for the weight table.
    float4* dst = out + (size_t)base_row * 256 + tid;
#pragma unroll
    for (int r = 0; r < ROWS_PER_CTA; r++) {
        stg_cs(dst, v[r]);
        dst += 256;
    }
}

extern "C" void kernel_launch(void* const* d_in, const int* in_sizes, int n_in,
                              void* d_out, int out_size)
{
    // metadata order: indices (int32, 8*2048), weight (float32, 50304*1024)
    const int*    indices = (const int*)d_in[0];
    const float4* weight  = (const float4*)d_in[1];
    float4*       out     = (float4*)d_out;

    const int rows = in_sizes[0];          // 16384
    gather_rows_kernel<<<rows / ROWS_PER_CTA, 256>>>(indices, weight, out);
}